// round 16
// baseline (speedup 1.0000x reference)
#include <cuda_runtime.h>
#include <cuda_fp16.h>
#include <math.h>
#include <cstdint>

#define NROWS   131072
#define KEMB    512
#define DIM     64
#define HW      4096
#define OUT_ELEMS 8388608LL
#define TILE_M  128
#define NTILES  (NROWS / TILE_M)     // 1024
#define CTAS    148
#define THREADS 512
#define XS_R    132                  // channel-major stride (floats)
#define XS_BUF_F (DIM * XS_R)        // 8448 floats = 33792 B
#define SCORE_BIAS 512.0f
#define REFINE_MARGIN 0.35f

// smem offsets (bytes)
#define OFF_BFRAG 0                  // 64*2*32 uint4 = 65536
#define OFF_XS    65536              // 3 * 33792 = 101376
#define OFF_NVB   166912             // 512*4
#define OFF_T3    168960             // 2(par) * 4 * 128 * 4 = 4096
#define OFF_CNT   173056             // 512*4
#define SMEM_TOTAL 175104

__device__ unsigned int g_counts[KEMB];
__device__ double g_sumsq;
__device__ int g_qn;                 // near-tie queue length
__device__ uint4 g_q[NROWS];         // (rowg, m1, m2, m3)

__device__ __forceinline__ void mma16816h(float* c, const uint32_t* a, uint32_t b0, uint32_t b1) {
    asm volatile(
        "mma.sync.aligned.m16n8k16.row.col.f32.f16.f16.f32 "
        "{%0,%1,%2,%3}, {%4,%5,%6,%7}, {%8,%9}, {%0,%1,%2,%3};"
        : "+f"(c[0]), "+f"(c[1]), "+f"(c[2]), "+f"(c[3])
        : "r"(a[0]), "r"(a[1]), "r"(a[2]), "r"(a[3]), "r"(b0), "r"(b1));
}

__device__ __forceinline__ uint32_t packh2(float a, float b) {
    __half2 h = __floats2half2_rn(a, b);
    return *reinterpret_cast<uint32_t*>(&h);
}

__device__ __forceinline__ uint32_t smem_u32(const void* p) {
    uint32_t a;
    asm("{ .reg .u64 t; cvta.to.shared.u64 t, %1; cvt.u32.u64 %0, t; }" : "=r"(a) : "l"(p));
    return a;
}

// min-ordered packed top-2 (packed u32: score-bits | idx; min = better)
#define T2_UPD(b1, b2, v) do { \
    uint32_t _t = max(b1, v); b1 = min(b1, v); b2 = min(b2, _t); } while (0)

#define T2_MERGE(b1, b2, o1, o2) do { \
    uint32_t _t = max(b1, o1); b1 = min(b1, o1); \
    uint32_t _u = min(b2, o2); b2 = min(_t, _u); } while (0)

// compensated accumulate of product x*e into (s,c)
#define CADD(s, c, xv, ev) do { \
    float _p  = __fmul_rn(xv, ev); \
    float _ep = fmaf(xv, ev, -_p); \
    float _z  = __fadd_rn(s, _p); \
    float _bv = __fsub_rn(_z, s); \
    float _er = __fadd_rn(__fsub_rn(s, __fsub_rn(_z, _bv)), __fsub_rn(_p, _bv)); \
    s = _z; c = __fadd_rn(c, __fadd_rn(_er, _ep)); } while (0)

extern __shared__ char s_raw[];

__device__ __forceinline__ void stage_async(const float* __restrict__ gbase,
                                            uint32_t smem_dst, int tid) {
    #pragma unroll
    for (int p = 0; p < 4; p++) {
        int idx = tid + p * THREADS;        // 2048 chunks of 16B
        int c = idx >> 5, q = idx & 31;
        uint32_t s = smem_dst + (uint32_t)(c * XS_R + 4 * q) * 4u;
        const float* g = gbase + (size_t)c * HW + 4 * q;
        asm volatile("cp.async.cg.shared.global [%0], [%1], 16;" :: "r"(s), "l"(g) : "memory");
    }
    asm volatile("cp.async.commit_group;" ::: "memory");
}

__global__ void __launch_bounds__(THREADS, 1)
vq_main(const float* __restrict__ in, const float* __restrict__ emb,
        float* __restrict__ outq, float* __restrict__ outidx)
{
    char* sm = s_raw;
    uint4* bfrag = reinterpret_cast<uint4*>(sm + OFF_BFRAG);
    float* xsall = reinterpret_cast<float*>(sm + OFF_XS);
    float* nvb   = reinterpret_cast<float*>(sm + OFF_NVB);
    uint32_t* t3 = reinterpret_cast<uint32_t*>(sm + OFF_T3);     // [2][4][128]
    unsigned int* scnt = reinterpret_cast<unsigned int*>(sm + OFF_CNT);
    const uint32_t smb_xs = smem_u32(sm + OFF_XS);

    const int tid = threadIdx.x;
    const int wid = tid >> 5, lane = tid & 31;
    const int lq = lane >> 2, lr = lane & 3;
    const int rg = wid >> 1;            // row-group 0..7
    const int nh = wid & 1;             // codebook half

    // ---- one-time: B fragments, biased norms, counts ----
    for (int i = tid; i < 64 * 2 * 32; i += THREADS) {
        int ln = i & 31, kp = (i >> 5) & 1, ns = i >> 6;
        int n  = ns * 8 + (ln >> 2);
        int k0 = kp * 32 + (ln & 3) * 2;
        const float* er = emb + n * DIM;
        bfrag[i] = make_uint4(
            packh2(er[k0],      er[k0 + 1]),
            packh2(er[k0 + 8],  er[k0 + 9]),
            packh2(er[k0 + 16], er[k0 + 17]),
            packh2(er[k0 + 24], er[k0 + 25]));
    }
    for (int k = tid; k < KEMB; k += THREADS) {
        const float* e = emb + k * DIM;
        float s = 0.f;
        #pragma unroll
        for (int d = 0; d < DIM; d++) s = fmaf(e[d], e[d], s);
        nvb[k] = s + SCORE_BIAS;
    }
    for (int i = tid; i < KEMB; i += THREADS) scnt[i] = 0u;

    // ---- prologue: stage first tile into buf 0 ----
    const int t0 = blockIdx.x;
    {
        const int b = t0 >> 5, hw0 = (t0 & 31) * TILE_M;
        stage_async(in + (size_t)b * (DIM * HW) + hw0, smb_xs, tid);
        asm volatile("cp.async.wait_all;" ::: "memory");
    }
    __syncthreads();

    int it = 0;
    for (int t = t0; t < NTILES; t += CTAS, it++) {
        const int cb = it - (it / 3) * 3;
        const float* xc = xsall + cb * XS_BUF_F;
        const int par = it & 1;

        // ---- A fragments from channel-major xs ----
        uint32_t a[4][4];
        {
            const int rl = rg * 16 + lq;
            #pragma unroll
            for (int ks = 0; ks < 4; ks++) {
                const int c0 = ks * 16 + lr * 2;
                const float* b0 = xc + c0 * XS_R;
                a[ks][0] = packh2(b0[rl],              b0[XS_R + rl]);
                a[ks][1] = packh2(b0[rl + 8],          b0[XS_R + rl + 8]);
                a[ks][2] = packh2(b0[8 * XS_R + rl],     b0[9 * XS_R + rl]);
                a[ks][3] = packh2(b0[8 * XS_R + rl + 8], b0[9 * XS_R + rl + 8]);
            }
        }

        // ---- prefetch next tile (hidden under mainloop) ----
        const int tn = t + CTAS;
        if (tn < NTILES) {
            const int nb = (it + 1) - ((it + 1) / 3) * 3;
            const int b = tn >> 5, hw0 = (tn & 31) * TILE_M;
            stage_async(in + (size_t)b * (DIM * HW) + hw0,
                        smb_xs + (uint32_t)nb * 33792u, tid);
        }

        // ---- main loop: 32 ns-steps, B prefetch, parity-split T2 ----
        uint32_t e1a = 0xFFFFFFFFu, e2a = 0xFFFFFFFFu;
        uint32_t d1a = 0xFFFFFFFFu, d2a = 0xFFFFFFFFu;
        uint32_t e1b = 0xFFFFFFFFu, e2b = 0xFFFFFFFFu;
        uint32_t d1b = 0xFFFFFFFFu, d2b = 0xFFFFFFFFu;
        const int ns0 = nh * 32;
        uint4 bA0 = bfrag[(ns0 * 2 + 0) * 32 + lane];
        uint4 bB0 = bfrag[(ns0 * 2 + 1) * 32 + lane];
        #pragma unroll 2
        for (int nsi = 0; nsi < 32; nsi++) {
            const int ns = ns0 + nsi;
            const int nsn = ns + (nsi < 31 ? 1 : 0);
            uint4 bA1 = bfrag[(nsn * 2 + 0) * 32 + lane];
            uint4 bB1 = bfrag[(nsn * 2 + 1) * 32 + lane];

            const int ka = ns * 8 + lr * 2;
            float2 nv = *reinterpret_cast<const float2*>(nvb + ka);

            float acc01[4] = {0.f, 0.f, 0.f, 0.f};
            float acc23[4] = {0.f, 0.f, 0.f, 0.f};
            mma16816h(acc01, a[0], bA0.x, bA0.y);
            mma16816h(acc23, a[2], bB0.x, bB0.y);
            mma16816h(acc01, a[1], bA0.z, bA0.w);
            mma16816h(acc23, a[3], bB0.z, bB0.w);

            float s0 = fmaf(-2.f, acc01[0] + acc23[0], nv.x);
            float s1 = fmaf(-2.f, acc01[1] + acc23[1], nv.y);
            float s2 = fmaf(-2.f, acc01[2] + acc23[2], nv.x);
            float s3 = fmaf(-2.f, acc01[3] + acc23[3], nv.y);
            uint32_t u0 = (__float_as_uint(s0) & 0xFFFFFE00u) | (uint32_t)ka;
            uint32_t u1 = (__float_as_uint(s1) & 0xFFFFFE00u) | (uint32_t)(ka + 1);
            uint32_t u2 = (__float_as_uint(s2) & 0xFFFFFE00u) | (uint32_t)ka;
            uint32_t u3 = (__float_as_uint(s3) & 0xFFFFFE00u) | (uint32_t)(ka + 1);
            if ((nsi & 1) == 0) {
                T2_UPD(e1a, e2a, u0); T2_UPD(e1a, e2a, u1);
                T2_UPD(e1b, e2b, u2); T2_UPD(e1b, e2b, u3);
            } else {
                T2_UPD(d1a, d2a, u0); T2_UPD(d1a, d2a, u1);
                T2_UPD(d1b, d2b, u2); T2_UPD(d1b, d2b, u3);
            }
            bA0 = bA1; bB0 = bB1;
        }
        uint32_t b1a = e1a, b2a = e2a, b1b = e1b, b2b = e2b;
        T2_MERGE(b1a, b2a, d1a, d2a);
        T2_MERGE(b1b, b2b, d1b, d2b);

        // ---- merge across 4 lanes sharing each row; write t3[par] ----
        #pragma unroll
        for (int off = 1; off <= 2; off <<= 1) {
            uint32_t o1 = __shfl_xor_sync(0xffffffffu, b1a, off);
            uint32_t o2 = __shfl_xor_sync(0xffffffffu, b2a, off);
            T2_MERGE(b1a, b2a, o1, o2);
            o1 = __shfl_xor_sync(0xffffffffu, b1b, off);
            o2 = __shfl_xor_sync(0xffffffffu, b2b, off);
            T2_MERGE(b1b, b2b, o1, o2);
        }
        if (lr == 0) {
            uint32_t* tp = t3 + par * 512;
            int ra = rg * 16 + lq, rb = ra + 8;
            tp[(nh * 2 + 0) * 128 + ra] = b1a;
            tp[(nh * 2 + 1) * 128 + ra] = b2a;
            tp[(nh * 2 + 0) * 128 + rb] = b1b;
            tp[(nh * 2 + 1) * 128 + rb] = b2b;
        }

        asm volatile("cp.async.wait_all;" ::: "memory");
        __syncthreads();   // t3[par] visible; next xs buffer complete

        // ---- fused epilogue (tid<128); refine DEFERRED to vq_fix ----
        if (tid < TILE_M) {
            const int r = tid;
            const uint32_t* tp = t3 + par * 512;
            uint32_t u1 = tp[r],       u2 = tp[128 + r];
            uint32_t o1 = tp[256 + r], o2 = tp[384 + r];
            // top-3 of the union of the two sorted pairs
            uint32_t m1 = min(u1, o1), tt = max(u1, o1);
            uint32_t uu = min(u2, o2), vv = max(u2, o2);
            uint32_t m2 = min(tt, uu);
            uint32_t m3 = min(max(tt, uu), vv);

            const int rowg = t * TILE_M + r;
            float s1f = __uint_as_float(m1 & 0xFFFFFE00u);
            float s2f = __uint_as_float(m2 & 0xFFFFFE00u);
            const int fbi = (int)(m1 & 511u);
            if (s2f - s1f < REFINE_MARGIN) {
                int slot = atomicAdd(&g_qn, 1);
                g_q[slot] = make_uint4((uint32_t)rowg, m1, m2, m3);
            }
            atomicAdd(&scnt[fbi], 1u);

            const int bb = rowg >> 12, hw = rowg & (HW - 1);
            if (outidx) outidx[rowg] = (float)fbi;

            float* xout = outq + (size_t)bb * (DIM * HW) + hw;
            const float4* q4 = reinterpret_cast<const float4*>(emb + fbi * DIM);
            const float* xcol = xc + r;
            float ssq = 0.f;
            #pragma unroll
            for (int i = 0; i < 16; i++) {
                float4 q = q4[i];
                float x0 = xcol[(4 * i + 0) * XS_R];
                float x1 = xcol[(4 * i + 1) * XS_R];
                float x2 = xcol[(4 * i + 2) * XS_R];
                float x3 = xcol[(4 * i + 3) * XS_R];
                float d0 = q.x - x0, d1 = q.y - x1, d2 = q.z - x2, d3 = q.w - x3;
                xout[(size_t)(4 * i + 0) * HW] = x0 + d0;
                xout[(size_t)(4 * i + 1) * HW] = x1 + d1;
                xout[(size_t)(4 * i + 2) * HW] = x2 + d2;
                xout[(size_t)(4 * i + 3) * HW] = x3 + d3;
                ssq = fmaf(d0, d0, ssq); ssq = fmaf(d1, d1, ssq);
                ssq = fmaf(d2, d2, ssq); ssq = fmaf(d3, d3, ssq);
            }
            #pragma unroll
            for (int off = 16; off > 0; off >>= 1)
                ssq += __shfl_down_sync(0xffffffffu, ssq, off);
            if (lane == 0) atomicAdd(&g_sumsq, (double)ssq);
        }
    }

    // flush per-CTA histogram
    __syncthreads();
    for (int i = tid; i < KEMB; i += THREADS)
        if (scnt[i]) atomicAdd(&g_counts[i], scnt[i]);
}

// Deferred exact rescore of queued near-tie rows; fixes outputs/counts/loss
// for the (rare) rows whose exact argmin differs from the fp16 leader.
__global__ void vq_fix(const float* __restrict__ in, const float* __restrict__ emb,
                       float* __restrict__ outq, float* __restrict__ outidx)
{
    const int n = g_qn;
    for (int i = blockIdx.x * blockDim.x + threadIdx.x; i < n;
         i += gridDim.x * blockDim.x) {
        uint4 e = g_q[i];
        const int rowg = (int)e.x;
        const int cand[3] = {(int)(e.y & 511u), (int)(e.z & 511u), (int)(e.w & 511u)};
        const int bb = rowg >> 12, hw = rowg & (HW - 1);
        const float* xin = in + (size_t)bb * (DIM * HW) + hw;

        float x[DIM];
        #pragma unroll
        for (int d = 0; d < DIM; d++) x[d] = xin[(size_t)d * HW];

        double bestd = 1e300; int besti = 0x7fffffff;
        #pragma unroll
        for (int c = 0; c < 3; c++) {
            const int k = cand[c];
            const float* ev = emb + k * DIM;
            float ds = 0.f, dc = 0.f, ns_ = 0.f, nc_ = 0.f;
            #pragma unroll
            for (int d = 0; d < DIM; d++) {
                CADD(ds, dc, x[d], ev[d]);
                CADD(ns_, nc_, ev[d], ev[d]);
            }
            double dist = ((double)ns_ + (double)nc_)
                        - 2.0 * ((double)ds + (double)dc);
            if (dist < bestd || (dist == bestd && k < besti)) { bestd = dist; besti = k; }
        }

        const int i1 = cand[0];
        if (besti != i1) {
            float* xout = outq + (size_t)bb * (DIM * HW) + hw;
            const float* qn_ = emb + besti * DIM;
            const float* qo_ = emb + i1 * DIM;
            float ssn = 0.f, sso = 0.f;
            #pragma unroll
            for (int d = 0; d < DIM; d++) {
                float dn = qn_[d] - x[d];
                float dold = qo_[d] - x[d];
                xout[(size_t)d * HW] = x[d] + dn;
                ssn = fmaf(dn, dn, ssn);
                sso = fmaf(dold, dold, sso);
            }
            atomicAdd(&g_sumsq, (double)ssn - (double)sso);
            atomicAdd(&g_counts[i1], 0xFFFFFFFFu);   // -1
            atomicAdd(&g_counts[besti], 1u);
            if (outidx) outidx[rowg] = (float)besti;
        }
    }
}

// fin: compute loss/perplexity, then reset globals for the next (graph) call
__global__ void vq_fin(float* loss_ptr, float* perp_ptr) {
    __shared__ float red[KEMB];
    const int t = threadIdx.x;
    float p = (float)g_counts[t] * (1.0f / (float)NROWS);
    red[t] = p * logf(p + 1e-10f);
    __syncthreads();
    #pragma unroll
    for (int s = KEMB / 2; s > 0; s >>= 1) {
        if (t < s) red[t] += red[t + s];
        __syncthreads();
    }
    if (t == 0) {
        if (perp_ptr) *perp_ptr = expf(-red[0]);
        if (loss_ptr) *loss_ptr = 0.25f * (float)(g_sumsq / (double)OUT_ELEMS);
        g_sumsq = 0.0;
        g_qn = 0;
    }
    g_counts[t] = 0u;
}

extern "C" void kernel_launch(void* const* d_in, const int* in_sizes, int n_in,
                              void* d_out, int out_size) {
    const float* in  = (const float*)d_in[0];
    const float* emb = (const float*)d_in[1];
    float* out = (float*)d_out;

    float* lossp = nullptr; float* perpp = nullptr; float* idxp = nullptr;
    float* outq = out;
    if ((long long)out_size == OUT_ELEMS) {
        outq = out;
    } else {
        lossp = out;
        outq  = out + 1;
        perpp = out + 1 + OUT_ELEMS;
        idxp  = perpp + 1;
    }

    cudaFuncSetAttribute(vq_main, cudaFuncAttributeMaxDynamicSharedMemorySize, SMEM_TOTAL);

    vq_main<<<CTAS, THREADS, SMEM_TOTAL>>>(in, emb, outq, idxp);
    vq_fix<<<CTAS, 256>>>(in, emb, outq, idxp);
    vq_fin<<<1, KEMB>>>(lossp, perpp);
}

// round 17
// speedup vs baseline: 1.2408x; 1.2408x over previous
#include <cuda_runtime.h>
#include <cuda_fp16.h>
#include <math.h>
#include <cstdint>

#define NROWS   131072
#define KEMB    512
#define DIM     64
#define HW      4096
#define OUT_ELEMS 8388608LL
#define TILE_M  128
#define NTILES  (NROWS / TILE_M)     // 1024
#define CTAS    148
#define THREADS 512
#define XS_R    132                  // channel-major stride (floats)
#define XS_BUF_F (DIM * XS_R)        // 8448 floats = 33792 B
#define SCORE_BIAS 512.0f
#define REFINE_MARGIN 0.20f

// smem offsets (bytes)
#define OFF_BFRAG 0                  // 64*2*32 uint4 = 65536
#define OFF_XS    65536              // 3 * 33792 = 101376
#define OFF_NVB   166912             // 512*4
#define OFF_T3    168960             // 2(par) * 4 * 128 * 4 = 4096
#define OFF_CNT   173056             // 512*4
#define SMEM_TOTAL 175104

__device__ unsigned int g_counts[KEMB];
__device__ double g_sumsq;
__device__ int g_qn;                 // near-tie queue length
__device__ uint4 g_q[NROWS];         // (rowg, m1, m2, m3)

__device__ __forceinline__ void mma16816h(float* c, const uint32_t* a, uint32_t b0, uint32_t b1) {
    asm volatile(
        "mma.sync.aligned.m16n8k16.row.col.f32.f16.f16.f32 "
        "{%0,%1,%2,%3}, {%4,%5,%6,%7}, {%8,%9}, {%0,%1,%2,%3};"
        : "+f"(c[0]), "+f"(c[1]), "+f"(c[2]), "+f"(c[3])
        : "r"(a[0]), "r"(a[1]), "r"(a[2]), "r"(a[3]), "r"(b0), "r"(b1));
}

__device__ __forceinline__ uint32_t packh2(float a, float b) {
    __half2 h = __floats2half2_rn(a, b);
    return *reinterpret_cast<uint32_t*>(&h);
}

__device__ __forceinline__ uint32_t smem_u32(const void* p) {
    uint32_t a;
    asm("{ .reg .u64 t; cvta.to.shared.u64 t, %1; cvt.u32.u64 %0, t; }" : "=r"(a) : "l"(p));
    return a;
}

// min-ordered packed top-2 (packed u32: score-bits | idx; min = better)
#define T2_UPD(b1, b2, v) do { \
    uint32_t _t = max(b1, v); b1 = min(b1, v); b2 = min(b2, _t); } while (0)

#define T2_MERGE(b1, b2, o1, o2) do { \
    uint32_t _t = max(b1, o1); b1 = min(b1, o1); \
    uint32_t _u = min(b2, o2); b2 = min(_t, _u); } while (0)

// compensated accumulate of product x*e into (s,c)
#define CADD(s, c, xv, ev) do { \
    float _p  = __fmul_rn(xv, ev); \
    float _ep = fmaf(xv, ev, -_p); \
    float _z  = __fadd_rn(s, _p); \
    float _bv = __fsub_rn(_z, s); \
    float _er = __fadd_rn(__fsub_rn(s, __fsub_rn(_z, _bv)), __fsub_rn(_p, _bv)); \
    s = _z; c = __fadd_rn(c, __fadd_rn(_er, _ep)); } while (0)

// TwoSum-combine (so,co) into (s,c)
#define TWOSUM(s, c, so, co) do { \
    float _z = __fadd_rn(s, so); \
    float _bv = __fsub_rn(_z, s); \
    float _er = __fadd_rn(__fsub_rn(s, __fsub_rn(_z, _bv)), __fsub_rn(so, _bv)); \
    s = _z; c = __fadd_rn(__fadd_rn(c, co), _er); } while (0)

extern __shared__ char s_raw[];

__device__ __forceinline__ void stage_async(const float* __restrict__ gbase,
                                            uint32_t smem_dst, int tid) {
    #pragma unroll
    for (int p = 0; p < 4; p++) {
        int idx = tid + p * THREADS;        // 2048 chunks of 16B
        int c = idx >> 5, q = idx & 31;
        uint32_t s = smem_dst + (uint32_t)(c * XS_R + 4 * q) * 4u;
        const float* g = gbase + (size_t)c * HW + 4 * q;
        asm volatile("cp.async.cg.shared.global [%0], [%1], 16;" :: "r"(s), "l"(g) : "memory");
    }
    asm volatile("cp.async.commit_group;" ::: "memory");
}

__global__ void __launch_bounds__(THREADS, 1)
vq_main(const float* __restrict__ in, const float* __restrict__ emb,
        float* __restrict__ outq, float* __restrict__ outidx)
{
    char* sm = s_raw;
    uint4* bfrag = reinterpret_cast<uint4*>(sm + OFF_BFRAG);
    float* xsall = reinterpret_cast<float*>(sm + OFF_XS);
    float* nvb   = reinterpret_cast<float*>(sm + OFF_NVB);
    uint32_t* t3 = reinterpret_cast<uint32_t*>(sm + OFF_T3);     // [2][4][128]
    unsigned int* scnt = reinterpret_cast<unsigned int*>(sm + OFF_CNT);
    const uint32_t smb_xs = smem_u32(sm + OFF_XS);

    const int tid = threadIdx.x;
    const int wid = tid >> 5, lane = tid & 31;
    const int lq = lane >> 2, lr = lane & 3;
    const int rg = wid >> 1;            // row-group 0..7
    const int nh = wid & 1;             // codebook half

    // ---- one-time: B fragments, biased norms, counts ----
    for (int i = tid; i < 64 * 2 * 32; i += THREADS) {
        int ln = i & 31, kp = (i >> 5) & 1, ns = i >> 6;
        int n  = ns * 8 + (ln >> 2);
        int k0 = kp * 32 + (ln & 3) * 2;
        const float* er = emb + n * DIM;
        bfrag[i] = make_uint4(
            packh2(er[k0],      er[k0 + 1]),
            packh2(er[k0 + 8],  er[k0 + 9]),
            packh2(er[k0 + 16], er[k0 + 17]),
            packh2(er[k0 + 24], er[k0 + 25]));
    }
    for (int k = tid; k < KEMB; k += THREADS) {
        const float* e = emb + k * DIM;
        float s = 0.f;
        #pragma unroll
        for (int d = 0; d < DIM; d++) s = fmaf(e[d], e[d], s);
        nvb[k] = s + SCORE_BIAS;
    }
    for (int i = tid; i < KEMB; i += THREADS) scnt[i] = 0u;

    // ---- prologue: stage first tile into buf 0 ----
    const int t0 = blockIdx.x;
    {
        const int b = t0 >> 5, hw0 = (t0 & 31) * TILE_M;
        stage_async(in + (size_t)b * (DIM * HW) + hw0, smb_xs, tid);
        asm volatile("cp.async.wait_all;" ::: "memory");
    }
    __syncthreads();

    int it = 0;
    for (int t = t0; t < NTILES; t += CTAS, it++) {
        const int cb = it - (it / 3) * 3;
        const float* xc = xsall + cb * XS_BUF_F;
        const int par = it & 1;

        // ---- A fragments from channel-major xs ----
        uint32_t a[4][4];
        {
            const int rl = rg * 16 + lq;
            #pragma unroll
            for (int ks = 0; ks < 4; ks++) {
                const int c0 = ks * 16 + lr * 2;
                const float* b0 = xc + c0 * XS_R;
                a[ks][0] = packh2(b0[rl],              b0[XS_R + rl]);
                a[ks][1] = packh2(b0[rl + 8],          b0[XS_R + rl + 8]);
                a[ks][2] = packh2(b0[8 * XS_R + rl],     b0[9 * XS_R + rl]);
                a[ks][3] = packh2(b0[8 * XS_R + rl + 8], b0[9 * XS_R + rl + 8]);
            }
        }

        // ---- prefetch next tile (hidden under mainloop) ----
        const int tn = t + CTAS;
        if (tn < NTILES) {
            const int nb = (it + 1) - ((it + 1) / 3) * 3;
            const int b = tn >> 5, hw0 = (tn & 31) * TILE_M;
            stage_async(in + (size_t)b * (DIM * HW) + hw0,
                        smb_xs + (uint32_t)nb * 33792u, tid);
        }

        // ---- main loop: 32 ns-steps, B prefetch, parity-split T2 ----
        uint32_t e1a = 0xFFFFFFFFu, e2a = 0xFFFFFFFFu;
        uint32_t d1a = 0xFFFFFFFFu, d2a = 0xFFFFFFFFu;
        uint32_t e1b = 0xFFFFFFFFu, e2b = 0xFFFFFFFFu;
        uint32_t d1b = 0xFFFFFFFFu, d2b = 0xFFFFFFFFu;
        const int ns0 = nh * 32;
        uint4 bA0 = bfrag[(ns0 * 2 + 0) * 32 + lane];
        uint4 bB0 = bfrag[(ns0 * 2 + 1) * 32 + lane];
        #pragma unroll 2
        for (int nsi = 0; nsi < 32; nsi++) {
            const int ns = ns0 + nsi;
            const int nsn = ns + (nsi < 31 ? 1 : 0);
            uint4 bA1 = bfrag[(nsn * 2 + 0) * 32 + lane];
            uint4 bB1 = bfrag[(nsn * 2 + 1) * 32 + lane];

            const int ka = ns * 8 + lr * 2;
            float2 nv = *reinterpret_cast<const float2*>(nvb + ka);

            float acc01[4] = {0.f, 0.f, 0.f, 0.f};
            float acc23[4] = {0.f, 0.f, 0.f, 0.f};
            mma16816h(acc01, a[0], bA0.x, bA0.y);
            mma16816h(acc23, a[2], bB0.x, bB0.y);
            mma16816h(acc01, a[1], bA0.z, bA0.w);
            mma16816h(acc23, a[3], bB0.z, bB0.w);

            float s0 = fmaf(-2.f, acc01[0] + acc23[0], nv.x);
            float s1 = fmaf(-2.f, acc01[1] + acc23[1], nv.y);
            float s2 = fmaf(-2.f, acc01[2] + acc23[2], nv.x);
            float s3 = fmaf(-2.f, acc01[3] + acc23[3], nv.y);
            uint32_t u0 = (__float_as_uint(s0) & 0xFFFFFE00u) | (uint32_t)ka;
            uint32_t u1 = (__float_as_uint(s1) & 0xFFFFFE00u) | (uint32_t)(ka + 1);
            uint32_t u2 = (__float_as_uint(s2) & 0xFFFFFE00u) | (uint32_t)ka;
            uint32_t u3 = (__float_as_uint(s3) & 0xFFFFFE00u) | (uint32_t)(ka + 1);
            if ((nsi & 1) == 0) {
                T2_UPD(e1a, e2a, u0); T2_UPD(e1a, e2a, u1);
                T2_UPD(e1b, e2b, u2); T2_UPD(e1b, e2b, u3);
            } else {
                T2_UPD(d1a, d2a, u0); T2_UPD(d1a, d2a, u1);
                T2_UPD(d1b, d2b, u2); T2_UPD(d1b, d2b, u3);
            }
            bA0 = bA1; bB0 = bB1;
        }
        uint32_t b1a = e1a, b2a = e2a, b1b = e1b, b2b = e2b;
        T2_MERGE(b1a, b2a, d1a, d2a);
        T2_MERGE(b1b, b2b, d1b, d2b);

        // ---- merge across 4 lanes sharing each row; write t3[par] ----
        #pragma unroll
        for (int off = 1; off <= 2; off <<= 1) {
            uint32_t o1 = __shfl_xor_sync(0xffffffffu, b1a, off);
            uint32_t o2 = __shfl_xor_sync(0xffffffffu, b2a, off);
            T2_MERGE(b1a, b2a, o1, o2);
            o1 = __shfl_xor_sync(0xffffffffu, b1b, off);
            o2 = __shfl_xor_sync(0xffffffffu, b2b, off);
            T2_MERGE(b1b, b2b, o1, o2);
        }
        if (lr == 0) {
            uint32_t* tp = t3 + par * 512;
            int ra = rg * 16 + lq, rb = ra + 8;
            tp[(nh * 2 + 0) * 128 + ra] = b1a;
            tp[(nh * 2 + 1) * 128 + ra] = b2a;
            tp[(nh * 2 + 0) * 128 + rb] = b1b;
            tp[(nh * 2 + 1) * 128 + rb] = b2b;
        }

        asm volatile("cp.async.wait_all;" ::: "memory");
        __syncthreads();   // t3[par] visible; next xs buffer complete

        // ---- fused epilogue (tid<128); refine DEFERRED to vq_fix ----
        if (tid < TILE_M) {
            const int r = tid;
            const uint32_t* tp = t3 + par * 512;
            uint32_t u1 = tp[r],       u2 = tp[128 + r];
            uint32_t o1 = tp[256 + r], o2 = tp[384 + r];
            // top-3 of the union of the two sorted pairs
            uint32_t m1 = min(u1, o1), tt = max(u1, o1);
            uint32_t uu = min(u2, o2), vv = max(u2, o2);
            uint32_t m2 = min(tt, uu);
            uint32_t m3 = min(max(tt, uu), vv);

            const int rowg = t * TILE_M + r;
            float s1f = __uint_as_float(m1 & 0xFFFFFE00u);
            float s2f = __uint_as_float(m2 & 0xFFFFFE00u);
            const int fbi = (int)(m1 & 511u);
            if (s2f - s1f < REFINE_MARGIN) {
                int slot = atomicAdd(&g_qn, 1);
                g_q[slot] = make_uint4((uint32_t)rowg, m1, m2, m3);
            }
            atomicAdd(&scnt[fbi], 1u);

            const int bb = rowg >> 12, hw = rowg & (HW - 1);
            if (outidx) outidx[rowg] = (float)fbi;

            float* xout = outq + (size_t)bb * (DIM * HW) + hw;
            const float4* q4 = reinterpret_cast<const float4*>(emb + fbi * DIM);
            const float* xcol = xc + r;
            float ssq = 0.f;
            #pragma unroll
            for (int i = 0; i < 16; i++) {
                float4 q = q4[i];
                float x0 = xcol[(4 * i + 0) * XS_R];
                float x1 = xcol[(4 * i + 1) * XS_R];
                float x2 = xcol[(4 * i + 2) * XS_R];
                float x3 = xcol[(4 * i + 3) * XS_R];
                float d0 = q.x - x0, d1 = q.y - x1, d2 = q.z - x2, d3 = q.w - x3;
                xout[(size_t)(4 * i + 0) * HW] = x0 + d0;
                xout[(size_t)(4 * i + 1) * HW] = x1 + d1;
                xout[(size_t)(4 * i + 2) * HW] = x2 + d2;
                xout[(size_t)(4 * i + 3) * HW] = x3 + d3;
                ssq = fmaf(d0, d0, ssq); ssq = fmaf(d1, d1, ssq);
                ssq = fmaf(d2, d2, ssq); ssq = fmaf(d3, d3, ssq);
            }
            #pragma unroll
            for (int off = 16; off > 0; off >>= 1)
                ssq += __shfl_down_sync(0xffffffffu, ssq, off);
            if (lane == 0) atomicAdd(&g_sumsq, (double)ssq);
        }
    }

    // flush per-CTA histogram
    __syncthreads();
    for (int i = tid; i < KEMB; i += THREADS)
        if (scnt[i]) atomicAdd(&g_counts[i], scnt[i]);
}

// Deferred exact rescore: 4 lanes per queued row (16 dims each), compensated
// dots combined exactly across lanes via TwoSum. Decision semantics identical
// to the validated in-kernel refine (tie -> smaller index).
__global__ void vq_fix(const float* __restrict__ in, const float* __restrict__ emb,
                       float* __restrict__ outq, float* __restrict__ outidx)
{
    const int n = g_qn;
    if (n == 0) return;
    const int gwarp = (blockIdx.x * blockDim.x + threadIdx.x) >> 5;
    const int nwarp = (gridDim.x * blockDim.x) >> 5;
    const int lane = threadIdx.x & 31;
    const int sub = lane >> 2, sl = lane & 3;

    for (int base = gwarp * 8; base < n; base += nwarp * 8) {
        const int i = base + sub;
        const bool act = (i < n);
        const uint4 e = g_q[act ? i : (n - 1)];
        const int rowg = (int)e.x;
        const int c0 = (int)(e.y & 511u), c1 = (int)(e.z & 511u), c2 = (int)(e.w & 511u);
        const int bb = rowg >> 12, hw = rowg & (HW - 1);
        const float* xin = in + (size_t)bb * (DIM * HW) + hw + (size_t)(sl * 16) * HW;

        float x[16];
        #pragma unroll
        for (int d = 0; d < 16; d++) x[d] = xin[(size_t)d * HW];

        float ds0 = 0.f, dc0 = 0.f, ns0 = 0.f, nc0 = 0.f;
        float ds1 = 0.f, dc1 = 0.f, ns1 = 0.f, nc1 = 0.f;
        float ds2 = 0.f, dc2 = 0.f, ns2 = 0.f, nc2 = 0.f;
        const float* e0 = emb + c0 * DIM + sl * 16;
        const float* e1 = emb + c1 * DIM + sl * 16;
        const float* e2 = emb + c2 * DIM + sl * 16;
        #pragma unroll
        for (int d = 0; d < 16; d++) {
            float v0 = e0[d], v1 = e1[d], v2 = e2[d];
            CADD(ds0, dc0, x[d], v0); CADD(ns0, nc0, v0, v0);
            CADD(ds1, dc1, x[d], v1); CADD(ns1, nc1, v1, v1);
            CADD(ds2, dc2, x[d], v2); CADD(ns2, nc2, v2, v2);
        }
        // exact cross-lane combine within each aligned 4-lane group
        #pragma unroll
        for (int off = 1; off <= 2; off <<= 1) {
            float so, co;
            so = __shfl_xor_sync(0xffffffffu, ds0, off);
            co = __shfl_xor_sync(0xffffffffu, dc0, off);
            TWOSUM(ds0, dc0, so, co);
            so = __shfl_xor_sync(0xffffffffu, ns0, off);
            co = __shfl_xor_sync(0xffffffffu, nc0, off);
            TWOSUM(ns0, nc0, so, co);
            so = __shfl_xor_sync(0xffffffffu, ds1, off);
            co = __shfl_xor_sync(0xffffffffu, dc1, off);
            TWOSUM(ds1, dc1, so, co);
            so = __shfl_xor_sync(0xffffffffu, ns1, off);
            co = __shfl_xor_sync(0xffffffffu, nc1, off);
            TWOSUM(ns1, nc1, so, co);
            so = __shfl_xor_sync(0xffffffffu, ds2, off);
            co = __shfl_xor_sync(0xffffffffu, dc2, off);
            TWOSUM(ds2, dc2, so, co);
            so = __shfl_xor_sync(0xffffffffu, ns2, off);
            co = __shfl_xor_sync(0xffffffffu, nc2, off);
            TWOSUM(ns2, nc2, so, co);
        }

        double d0 = ((double)ns0 + (double)nc0) - 2.0 * ((double)ds0 + (double)dc0);
        double d1 = ((double)ns1 + (double)nc1) - 2.0 * ((double)ds1 + (double)dc1);
        double d2 = ((double)ns2 + (double)nc2) - 2.0 * ((double)ds2 + (double)dc2);
        double bd = d0; int besti = c0;
        if (d1 < bd || (d1 == bd && c1 < besti)) { bd = d1; besti = c1; }
        if (d2 < bd || (d2 == bd && c2 < besti)) { bd = d2; besti = c2; }

        if (act && besti != c0) {
            float* xout = outq + (size_t)bb * (DIM * HW) + hw + (size_t)(sl * 16) * HW;
            const float* qn_ = emb + besti * DIM + sl * 16;
            const float* qo_ = emb + c0 * DIM + sl * 16;
            float ssn = 0.f, sso = 0.f;
            #pragma unroll
            for (int d = 0; d < 16; d++) {
                float dn = qn_[d] - x[d];
                float dold = qo_[d] - x[d];
                xout[(size_t)d * HW] = x[d] + dn;
                ssn = fmaf(dn, dn, ssn);
                sso = fmaf(dold, dold, sso);
            }
            atomicAdd(&g_sumsq, (double)ssn - (double)sso);
            if (sl == 0) {
                atomicAdd(&g_counts[c0], 0xFFFFFFFFu);   // -1
                atomicAdd(&g_counts[besti], 1u);
                if (outidx) outidx[rowg] = (float)besti;
            }
        }
    }
}

// fin: compute loss/perplexity, then reset globals for the next (graph) call
__global__ void vq_fin(float* loss_ptr, float* perp_ptr) {
    __shared__ float red[KEMB];
    const int t = threadIdx.x;
    float p = (float)g_counts[t] * (1.0f / (float)NROWS);
    red[t] = p * logf(p + 1e-10f);
    __syncthreads();
    #pragma unroll
    for (int s = KEMB / 2; s > 0; s >>= 1) {
        if (t < s) red[t] += red[t + s];
        __syncthreads();
    }
    if (t == 0) {
        if (perp_ptr) *perp_ptr = expf(-red[0]);
        if (loss_ptr) *loss_ptr = 0.25f * (float)(g_sumsq / (double)OUT_ELEMS);
        g_sumsq = 0.0;
        g_qn = 0;
    }
    g_counts[t] = 0u;
}

extern "C" void kernel_launch(void* const* d_in, const int* in_sizes, int n_in,
                              void* d_out, int out_size) {
    const float* in  = (const float*)d_in[0];
    const float* emb = (const float*)d_in[1];
    float* out = (float*)d_out;

    float* lossp = nullptr; float* perpp = nullptr; float* idxp = nullptr;
    float* outq = out;
    if ((long long)out_size == OUT_ELEMS) {
        outq = out;
    } else {
        lossp = out;
        outq  = out + 1;
        perpp = out + 1 + OUT_ELEMS;
        idxp  = perpp + 1;
    }

    cudaFuncSetAttribute(vq_main, cudaFuncAttributeMaxDynamicSharedMemorySize, SMEM_TOTAL);

    vq_main<<<CTAS, THREADS, SMEM_TOTAL>>>(in, emb, outq, idxp);
    vq_fix<<<CTAS, 256>>>(in, emb, outq, idxp);
    vq_fin<<<1, KEMB>>>(lossp, perpp);
}